// round 14
// baseline (speedup 1.0000x reference)
#include <cuda_runtime.h>
#include <cstdint>

// ColumnConsistencyLoss — streaming rewrite (no scattered gather).
// loss = mean over columns with n>1 of (q_c - |s_c|^2/n_c) / (n_c * C)
// Each CTA streams its CONTIGUOUS token slice (coalesced), computes softmax
// into a smem P-tile, and owner-warps (warp w owns columns 4w..4w+3) pull
// matching rows from smem into register accumulators. Per-CTA partials go to
// g_S[col][cta][dim]; after one grid barrier, CTA c reduces its contiguous
// 64KB and finalizes. Scattered DRAM access is eliminated entirely.

#define C_DIM     128
#define NCTA      128
#define NWARPS    32
#define NTHREADS  (NWARPS * 32)   // 1024
#define TILE      128             // tokens per tile (P tile = 64KB fp32)
#define DET_WORDS 2048
#define META_W    1024            // smem meta words (supports per-CTA <= 4096 tokens)

__device__ float    g_S[(size_t)C_DIM * NCTA * C_DIM];  // [col][cta][dim], 8MB
__device__ float    g_Q[C_DIM * NCTA];                  // [col][cta]
__device__ float    g_N[C_DIM * NCTA];                  // [col][cta]
__device__ float    g_total;
__device__ int      g_cnt;
__device__ unsigned g_done;
__device__ unsigned g_bar;

__device__ __forceinline__ float warp_sum(float x) {
    x += __shfl_xor_sync(0xffffffffu, x, 16);
    x += __shfl_xor_sync(0xffffffffu, x, 8);
    x += __shfl_xor_sync(0xffffffffu, x, 4);
    x += __shfl_xor_sync(0xffffffffu, x, 2);
    x += __shfl_xor_sync(0xffffffffu, x, 1);
    return x;
}

__global__ void __launch_bounds__(NTHREADS, 1)
fused_kernel(const float* __restrict__ logits, const int* __restrict__ seg,
             const void* __restrict__ mask, float* __restrict__ out, int n)
{
    extern __shared__ float Ptile[];            // TILE*C_DIM fp32 = 64KB dynamic
    __shared__ unsigned s_meta[META_W];         // 4KB: (seg|valid<<7) per token
    __shared__ float    s_part[8 * C_DIM];      // 4KB reduction scratch
    __shared__ float    s_red[4], s_redq[4], s_redn[4];

    int tid  = threadIdx.x;
    int lane = tid & 31;
    int warp = tid >> 5;
    int bid  = blockIdx.x;
    int c    = bid;

    // Per-CTA contiguous slice, padded to whole tiles.
    int per    = (n + NCTA - 1) / NCTA;
    int ntiles = (per + TILE - 1) / TILE;
    per = ntiles * TILE;                        // disjoint [bid*per,(bid+1)*per)
    size_t start = (size_t)bid * per;

    // ---- Phase 0: redundant local mask-dtype detection. ----
    const unsigned* mwp = (const unsigned*)mask;
    int detw = min(DET_WORDS, n >> 2);
    int f_gt1 = 0, f_off = 0;
    for (int i = tid; i < detw; i += NTHREADS) {
        unsigned w = mwp[i];
        f_gt1 |= ((w & 0xFEFEFEFEu) != 0u);   // byte >= 2      -> float32 mask
        f_off |= ((w & 0xFFFFFF00u) != 0u);   // nonzero b1..b3 -> uint8 mask
    }
    int m_gt1 = __syncthreads_or(f_gt1);
    int m_off = __syncthreads_or(f_off);

    // ---- Phase 1: build CTA-local meta (seg|valid<<7 per token). ----
    {
        const int4*     sg4 = (const int4*)seg;
        const float4*   mf4 = (const float4*)mask;
        const unsigned* mu  = (const unsigned*)mask;
        const int4*     mi4 = (const int4*)mask;
        int nw4 = per >> 2;
        for (int i = tid; i < nw4; i += NTHREADS) {
            size_t gw = (start >> 2) + i;
            size_t gt = start + 4 * (size_t)i;
            unsigned mword;
            if (gt + 3 < (size_t)n) {
                int4 s4 = sg4[gw];
                unsigned vm;
                if (m_gt1) {
                    float4 m4 = mf4[gw];
                    vm = (m4.x != 0.0f ? 1u : 0u) | (m4.y != 0.0f ? 2u : 0u)
                       | (m4.z != 0.0f ? 4u : 0u) | (m4.w != 0.0f ? 8u : 0u);
                } else if (m_off) {
                    unsigned m4 = mu[gw];
                    vm = ((m4 & 0x000000FFu) ? 1u : 0u) | ((m4 & 0x0000FF00u) ? 2u : 0u)
                       | ((m4 & 0x00FF0000u) ? 4u : 0u) | ((m4 & 0xFF000000u) ? 8u : 0u);
                } else {
                    int4 m4 = mi4[gw];
                    vm = (m4.x ? 1u : 0u) | (m4.y ? 2u : 0u)
                       | (m4.z ? 4u : 0u) | (m4.w ? 8u : 0u);
                }
                unsigned b0 = (unsigned)(s4.x & 127) | ((vm & 1u) << 7);
                unsigned b1 = (unsigned)(s4.y & 127) | ((vm & 2u) << 6);
                unsigned b2 = (unsigned)(s4.z & 127) | ((vm & 4u) << 5);
                unsigned b3 = (unsigned)(s4.w & 127) | ((vm & 8u) << 4);
                mword = b0 | (b1 << 8) | (b2 << 16) | (b3 << 24);
            } else {
                mword = 0;
                for (int b = 0; b < 4; b++) {
                    size_t t = gt + b;
                    if (t < (size_t)n) {
                        int valid;
                        if (m_gt1)      valid = (((const float*)mask)[t] != 0.0f);
                        else if (m_off) valid = (((const unsigned char*)mask)[t] != 0);
                        else            valid = (((const int*)mask)[t] != 0);
                        mword |= ((unsigned)(seg[t] & 127) | ((unsigned)valid << 7)) << (8 * b);
                    }
                }
            }
            s_meta[i] = mword;
        }
    }
    __syncthreads();

    // ---- Phase 2: tile loop — produce (coalesced) then owner-accumulate. ----
    const unsigned char* metab = (const unsigned char*)s_meta;
    float4* P4 = (float4*)Ptile;
    const float4* lg4 = (const float4*)logits;

    float4 s0 = {0,0,0,0}, s1 = {0,0,0,0}, s2 = {0,0,0,0}, s3 = {0,0,0,0};
    float q0 = 0.f, q1 = 0.f, q2 = 0.f, q3 = 0.f;
    int   n0 = 0, n1 = 0, n2 = 0, n3 = 0;
    unsigned key = 0x20u | (unsigned)warp;      // (meta_byte>>2) for my 4 cols

    for (int tile = 0; tile < ntiles; tile++) {
        // -- Produce: warp handles tokens {tile*128 + warp + 32j}. Valid only. --
        int tb = tile * TILE;
        unsigned vmask = 0;
        float4 v[4];
        #pragma unroll
        for (int j = 0; j < 4; j++) {
            int tt = tb + warp + 32 * j;
            if (metab[tt] & 0x80u) {
                vmask |= (1u << j);
                v[j] = lg4[(start + tt) * 32 + lane];
            }
        }
        float z[4];
        #pragma unroll
        for (int j = 0; j < 4; j++) {
            if (vmask & (1u << j)) {
                v[j].x = __expf(v[j].x);
                v[j].y = __expf(v[j].y);
                v[j].z = __expf(v[j].z);
                v[j].w = __expf(v[j].w);
                z[j] = (v[j].x + v[j].y) + (v[j].z + v[j].w);
            } else z[j] = 1.f;
        }
        #pragma unroll
        for (int off = 16; off; off >>= 1) {
            #pragma unroll
            for (int j = 0; j < 4; j++)
                z[j] += __shfl_xor_sync(0xffffffffu, z[j], off);
        }
        #pragma unroll
        for (int j = 0; j < 4; j++) {
            if (vmask & (1u << j)) {
                float r = __fdividef(1.0f, z[j]);
                float4 p;
                p.x = v[j].x * r; p.y = v[j].y * r;
                p.z = v[j].z * r; p.w = v[j].w * r;
                P4[(warp + 32 * j) * 32 + lane] = p;
            }
        }
        __syncthreads();

        // -- Accumulate: pull rows of my 4 columns from the P tile. --
        unsigned word = s_meta[tile * 32 + lane];   // lane's 4 tokens
        unsigned my = 0;
        #pragma unroll
        for (int b = 0; b < 4; b++)
            my |= (((word >> (8 * b)) & 0xFFu) >> 2 == key) ? 1u : 0u;
        unsigned bal = __ballot_sync(0xffffffffu, my);
        while (bal) {
            int src = __ffs(bal) - 1;
            bal &= bal - 1;
            unsigned mw = __shfl_sync(0xffffffffu, word, src);
            int base = src * 4;
            #pragma unroll
            for (int b = 0; b < 4; b++) {
                unsigned byte = (mw >> (8 * b)) & 0xFFu;
                if ((byte >> 2) == key) {                 // valid & my column
                    int kk = byte & 3;                    // warp-uniform
                    float4 pv = P4[(base + b) * 32 + lane];
                    float dq = pv.x*pv.x + pv.y*pv.y + pv.z*pv.z + pv.w*pv.w;
                    if (kk == 0)      { s0.x+=pv.x; s0.y+=pv.y; s0.z+=pv.z; s0.w+=pv.w; q0+=dq; n0++; }
                    else if (kk == 1) { s1.x+=pv.x; s1.y+=pv.y; s1.z+=pv.z; s1.w+=pv.w; q1+=dq; n1++; }
                    else if (kk == 2) { s2.x+=pv.x; s2.y+=pv.y; s2.z+=pv.z; s2.w+=pv.w; q2+=dq; n2++; }
                    else              { s3.x+=pv.x; s3.y+=pv.y; s3.z+=pv.z; s3.w+=pv.w; q3+=dq; n3++; }
                }
            }
        }
        __syncthreads();   // P tile free for next produce
    }

    // ---- Phase 3: write per-CTA partials (coalesced). ----
    {
        int c0 = 4 * warp;
        ((float4*)&g_S[((size_t)(c0 + 0) * NCTA + bid) * C_DIM])[lane] = s0;
        ((float4*)&g_S[((size_t)(c0 + 1) * NCTA + bid) * C_DIM])[lane] = s1;
        ((float4*)&g_S[((size_t)(c0 + 2) * NCTA + bid) * C_DIM])[lane] = s2;
        ((float4*)&g_S[((size_t)(c0 + 3) * NCTA + bid) * C_DIM])[lane] = s3;
        float qs0 = warp_sum(q0), qs1 = warp_sum(q1);
        float qs2 = warp_sum(q2), qs3 = warp_sum(q3);
        if (lane == 0) {
            g_Q[(c0 + 0) * NCTA + bid] = qs0;  g_N[(c0 + 0) * NCTA + bid] = (float)n0;
            g_Q[(c0 + 1) * NCTA + bid] = qs1;  g_N[(c0 + 1) * NCTA + bid] = (float)n1;
            g_Q[(c0 + 2) * NCTA + bid] = qs2;  g_N[(c0 + 2) * NCTA + bid] = (float)n2;
            g_Q[(c0 + 3) * NCTA + bid] = qs3;  g_N[(c0 + 3) * NCTA + bid] = (float)n3;
        }
    }

    // ---- Grid barrier (128 CTAs co-resident). ----
    __syncthreads();
    if (tid == 0) {
        __threadfence();                        // publish partials
        atomicAdd(&g_bar, 1u);
        while (*((volatile unsigned*)&g_bar) < (unsigned)NCTA) __nanosleep(32);
        __threadfence();                        // acquire
    }
    __syncthreads();

    // ---- Phase 4: CTA c reduces its contiguous 64KB of partials. ----
    {
        const float* Sc = g_S + (size_t)c * NCTA * C_DIM;
        int d  = tid & 127;
        int gg = tid >> 7;                      // 8 groups of 16 CTAs
        float sum = 0.f;
        #pragma unroll 4
        for (int j = 0; j < NCTA / 8; j++)
            sum += Sc[(size_t)(gg * (NCTA / 8) + j) * C_DIM + d];
        s_part[gg * C_DIM + d] = sum;
    }
    __syncthreads();

    float v2n = 0.f, qv = 0.f, nv = 0.f;
    if (tid < C_DIM) {
        float sd = 0.f;
        #pragma unroll
        for (int g = 0; g < 8; g++) sd += s_part[g * C_DIM + tid];
        v2n = sd * sd;
        qv = g_Q[c * NCTA + tid];
        nv = g_N[c * NCTA + tid];
    }
    v2n = warp_sum(v2n); qv = warp_sum(qv); nv = warp_sum(nv);
    if (tid < C_DIM && lane == 0) { s_red[warp] = v2n; s_redq[warp] = qv; s_redn[warp] = nv; }
    __syncthreads();

    if (tid == 0) {
        float snorm2 = (s_red[0] + s_red[1]) + (s_red[2] + s_red[3]);
        float q      = (s_redq[0] + s_redq[1]) + (s_redq[2] + s_redq[3]);
        float fn     = (s_redn[0] + s_redn[1]) + (s_redn[2] + s_redn[3]);
        if (fn > 1.0f) {
            float var = (q - snorm2 / fn) / (fn * (float)C_DIM);
            atomicAdd(&g_total, var);
            atomicAdd(&g_cnt, 1);
        }
        __threadfence();
        unsigned d = atomicAdd(&g_done, 1u);
        if (d == (unsigned)(NCTA - 1)) {
            float tot = atomicExch(&g_total, 0.f);
            int   cc  = atomicExch(&g_cnt, 0);
            out[0] = (cc > 0) ? (tot / (float)cc) : 0.f;
            g_bar  = 0u;                        // reset for next graph replay
            atomicExch(&g_done, 0u);
        }
    }
}

extern "C" void kernel_launch(void* const* d_in, const int* in_sizes, int n_in,
                              void* d_out, int out_size) {
    const float* logits = (const float*)d_in[0];
    const int*   seg    = (const int*)d_in[1];
    const void*  mask   = d_in[2];
    int n = in_sizes[1];                 // B*T tokens
    (void)n_in; (void)out_size;

    cudaFuncSetAttribute(fused_kernel,
                         cudaFuncAttributeMaxDynamicSharedMemorySize,
                         TILE * C_DIM * 4);
    fused_kernel<<<NCTA, NTHREADS, TILE * C_DIM * 4>>>(logits, seg, mask,
                                                       (float*)d_out, n);
}